// round 1
// baseline (speedup 1.0000x reference)
#include <cuda_runtime.h>
#include <cuda_bf16.h>

// y = (x @ Wd^T + s*(x @ A^T) @ B^T) * mag + bias
// x:  [M, 1024]  (M = 8*197 = 1576)
// Wd: [4096, 1024]
// mag:[4096, 1]
// A:  [16, 1024]
// B:  [4096, 16]
// bias: [4096]

#define IN_F   1024
#define OUT_F  4096
#define RANK   16
#define LORA_SCALE 0.8f

#define BM 128
#define BN 128
#define BK 8
#define TM 8
#define TN 8
// 256 threads: 16x16 thread grid of 8x8 micro-tiles

// scratch for t = s*(x @ A^T), [M, 16]
__device__ float g_t[65536];  // supports M up to 4096

// ---------------------------------------------------------------------------
// Kernel A: t[m, r] = LORA_SCALE * sum_k x[m,k] * A[r,k]
// grid = M blocks, 128 threads
// ---------------------------------------------------------------------------
__global__ void lora_t_kernel(const float* __restrict__ x,
                              const float* __restrict__ loraA,
                              float* __restrict__ t, int M) {
    int m = blockIdx.x;
    if (m >= M) return;
    const float* xrow = x + (size_t)m * IN_F;

    float sum[RANK];
#pragma unroll
    for (int r = 0; r < RANK; r++) sum[r] = 0.f;

    for (int k = threadIdx.x; k < IN_F; k += 128) {
        float xv = xrow[k];
#pragma unroll
        for (int r = 0; r < RANK; r++) {
            sum[r] += xv * loraA[r * IN_F + k];
        }
    }

    __shared__ float sm[128 * RANK];
#pragma unroll
    for (int r = 0; r < RANK; r++) sm[threadIdx.x * RANK + r] = sum[r];
    __syncthreads();

    if (threadIdx.x < RANK) {
        int r = threadIdx.x;
        float s = 0.f;
        for (int i = 0; i < 128; i++) s += sm[i * RANK + r];
        t[m * RANK + r] = s * LORA_SCALE;
    }
}

// ---------------------------------------------------------------------------
// Kernel B: main GEMM with fused rank-16 + mag/bias epilogue
// ---------------------------------------------------------------------------
__global__ __launch_bounds__(256, 2)
void dora_gemm_kernel(const float* __restrict__ x,
                      const float* __restrict__ wd,
                      const float* __restrict__ mag,
                      const float* __restrict__ loraB,
                      const float* __restrict__ bias,
                      const float* __restrict__ t,
                      float* __restrict__ out, int M) {
    __shared__ float smem[4096];  // 16 KB, aliased between mainloop and epilogue
    float* As = smem;             // [BK][BM] = 1024 floats
    float* Bs = smem + 1024;      // [BK][BN] = 1024 floats

    const int tid = threadIdx.x;
    const int bm = blockIdx.y * BM;   // row tile (M)
    const int bn = blockIdx.x * BN;   // col tile (N)

    const int tx = tid & 15;   // 0..15 -> col group
    const int ty = tid >> 4;   // 0..15 -> row group

    // load mapping: 2 threads per 128-row tile row, each loads a float4 (BK=8)
    const int ldRow = tid >> 1;          // 0..127
    const int ldCol = (tid & 1) * 4;     // 0 or 4

    float acc[TM][TN];
#pragma unroll
    for (int i = 0; i < TM; i++)
#pragma unroll
        for (int j = 0; j < TN; j++) acc[i][j] = 0.f;

    const int aRowG = bm + ldRow;           // global x row for A-tile loads
    const bool aValid = (aRowG < M);
    const float* xBase  = x  + (size_t)aRowG * IN_F + ldCol;
    const float* wdBase = wd + (size_t)(bn + ldRow) * IN_F + ldCol;

    for (int k0 = 0; k0 < IN_F; k0 += BK) {
        // load x tile (transpose into As[kk][m])
        float4 av;
        if (aValid) av = *reinterpret_cast<const float4*>(xBase + k0);
        else        av = make_float4(0.f, 0.f, 0.f, 0.f);
        As[(ldCol + 0) * BM + ldRow] = av.x;
        As[(ldCol + 1) * BM + ldRow] = av.y;
        As[(ldCol + 2) * BM + ldRow] = av.z;
        As[(ldCol + 3) * BM + ldRow] = av.w;

        // load Wd tile (transpose into Bs[kk][o]) — N=4096 always in-bounds
        float4 bv = *reinterpret_cast<const float4*>(wdBase + k0);
        Bs[(ldCol + 0) * BN + ldRow] = bv.x;
        Bs[(ldCol + 1) * BN + ldRow] = bv.y;
        Bs[(ldCol + 2) * BN + ldRow] = bv.z;
        Bs[(ldCol + 3) * BN + ldRow] = bv.w;

        __syncthreads();

#pragma unroll
        for (int kk = 0; kk < BK; kk++) {
            float ar[TM], br[TN];
#pragma unroll
            for (int i = 0; i < TM; i++) ar[i] = As[kk * BM + ty * TM + i];
#pragma unroll
            for (int j = 0; j < TN; j++) br[j] = Bs[kk * BN + tx * TN + j];
#pragma unroll
            for (int i = 0; i < TM; i++)
#pragma unroll
                for (int j = 0; j < TN; j++)
                    acc[i][j] += ar[i] * br[j];
        }
        __syncthreads();
    }

    // ---------------- epilogue: + t @ B^T, then *mag + bias ----------------
    // reuse smem: ts[BM][16] then bs2[16][BN]
    float* ts  = smem;          // 2048 floats
    float* bs2 = smem + 2048;   // 2048 floats

    for (int idx = tid; idx < BM * RANK; idx += 256) {
        int ml = idx >> 4, r = idx & 15;
        int mg = bm + ml;
        ts[ml * RANK + r] = (mg < M) ? t[mg * RANK + r] : 0.f;
    }
    for (int idx = tid; idx < BN * RANK; idx += 256) {
        int ol = idx >> 4, r = idx & 15;
        bs2[r * BN + ol] = loraB[(size_t)(bn + ol) * RANK + r];
    }
    __syncthreads();

#pragma unroll
    for (int r = 0; r < RANK; r++) {
        float ta[TM], bb[TN];
#pragma unroll
        for (int i = 0; i < TM; i++) ta[i] = ts[(ty * TM + i) * RANK + r];
#pragma unroll
        for (int j = 0; j < TN; j++) bb[j] = bs2[r * BN + tx * TN + j];
#pragma unroll
        for (int i = 0; i < TM; i++)
#pragma unroll
            for (int j = 0; j < TN; j++)
                acc[i][j] += ta[i] * bb[j];
    }

    // mag + bias, vectorized store (cols are contiguous groups of 8)
    float magv[TN], bv2[TN];
#pragma unroll
    for (int j = 0; j < TN; j++) {
        int o = bn + tx * TN + j;
        magv[j] = mag[o];
        bv2[j]  = bias[o];
    }

#pragma unroll
    for (int i = 0; i < TM; i++) {
        int mg = bm + ty * TM + i;
        if (mg >= M) continue;
        float* orow = out + (size_t)mg * OUT_F + bn + tx * TN;
        float4 v0, v1;
        v0.x = acc[i][0] * magv[0] + bv2[0];
        v0.y = acc[i][1] * magv[1] + bv2[1];
        v0.z = acc[i][2] * magv[2] + bv2[2];
        v0.w = acc[i][3] * magv[3] + bv2[3];
        v1.x = acc[i][4] * magv[4] + bv2[4];
        v1.y = acc[i][5] * magv[5] + bv2[5];
        v1.z = acc[i][6] * magv[6] + bv2[6];
        v1.w = acc[i][7] * magv[7] + bv2[7];
        *reinterpret_cast<float4*>(orow)     = v0;
        *reinterpret_cast<float4*>(orow + 4) = v1;
    }
}

extern "C" void kernel_launch(void* const* d_in, const int* in_sizes, int n_in,
                              void* d_out, int out_size) {
    const float* x     = (const float*)d_in[0];
    const float* wd    = (const float*)d_in[1];
    const float* mag   = (const float*)d_in[2];
    const float* loraA = (const float*)d_in[3];
    const float* loraB = (const float*)d_in[4];
    const float* bias  = (const float*)d_in[5];
    float* out = (float*)d_out;

    const int M = in_sizes[0] / IN_F;

    float* t;
    cudaGetSymbolAddress((void**)&t, g_t);

    lora_t_kernel<<<M, 128>>>(x, loraA, t, M);

    dim3 grid(OUT_F / BN, (M + BM - 1) / BM);
    dora_gemm_kernel<<<grid, 256>>>(x, wd, mag, loraB, bias, t, out, M);
}

// round 2
// speedup vs baseline: 2.4467x; 2.4467x over previous
#include <cuda_runtime.h>
#include <cuda_bf16.h>
#include <cstdint>

// y = (x @ Wd^T + s*(x @ A^T) @ B^T) * mag + bias
// x: [M,1024], Wd: [4096,1024], mag: [4096,1], A: [16,1024], B: [4096,16], bias: [4096]

#define IN_F   1024
#define OUT_F  4096
#define RANK   16
#define LORA_SCALE 0.8f

#define BM 128
#define BN 128
#define BK 16
#define STAGES 3

__device__ float g_t[65536];  // t = s*(x @ A^T), [M,16], M<=4096

// ---------------------------------------------------------------------------
// helpers
// ---------------------------------------------------------------------------
__device__ __forceinline__ uint32_t smem_u32(const void* p) {
    return (uint32_t)__cvta_generic_to_shared(p);
}
__device__ __forceinline__ void cp_async16(uint32_t dst, const void* src, int src_bytes) {
    asm volatile("cp.async.cg.shared.global [%0], [%1], 16, %2;\n"
                 :: "r"(dst), "l"(src), "r"(src_bytes));
}
__device__ __forceinline__ void cp_commit() { asm volatile("cp.async.commit_group;\n"); }
template <int N>
__device__ __forceinline__ void cp_wait() { asm volatile("cp.async.wait_group %0;\n" :: "n"(N)); }

__device__ __forceinline__ uint32_t f2tf32(float f) {
    uint32_t r;
    asm("cvt.rna.tf32.f32 %0, %1;" : "=r"(r) : "f"(f));
    return r;
}

// swizzled scalar address inside a [row][16] tile: float4-group XOR key (row>>1)&3
__device__ __forceinline__ int sw_addr(int row, int k) {
    int c4 = k >> 2;
    int sw = c4 ^ ((row >> 1) & 3);
    return row * 16 + (sw << 2) + (k & 3);
}

// ---------------------------------------------------------------------------
// Kernel A: t[m,r] = LORA_SCALE * sum_k x[m,k]*A[r,k]
// 256 threads = (16 ranks) x (16 row-groups), 2 rows/thread, 32 rows/block
// ---------------------------------------------------------------------------
__global__ void lora_t_kernel(const float* __restrict__ x,
                              const float* __restrict__ loraA,
                              float* __restrict__ t, int M) {
    const int tx = threadIdx.x & 15;   // rank
    const int ty = threadIdx.x >> 4;
    const int m0 = blockIdx.x * 32 + ty * 2;
    const bool v0 = m0 < M, v1 = (m0 + 1) < M;

    const float* ar = loraA + (size_t)tx * IN_F;
    const float* x0 = x + (size_t)m0 * IN_F;
    const float* x1 = x0 + IN_F;

    float s00 = 0.f, s01 = 0.f, s10 = 0.f, s11 = 0.f;
    for (int k = 0; k < IN_F; k += 4) {
        float4 a4 = *(const float4*)(ar + k);
        float4 p0 = v0 ? *(const float4*)(x0 + k) : make_float4(0,0,0,0);
        float4 p1 = v1 ? *(const float4*)(x1 + k) : make_float4(0,0,0,0);
        s00 += a4.x * p0.x + a4.y * p0.y;
        s01 += a4.z * p0.z + a4.w * p0.w;
        s10 += a4.x * p1.x + a4.y * p1.y;
        s11 += a4.z * p1.z + a4.w * p1.w;
    }
    if (v0) t[m0 * RANK + tx]       = (s00 + s01) * LORA_SCALE;
    if (v1) t[(m0 + 1) * RANK + tx] = (s10 + s11) * LORA_SCALE;
}

// ---------------------------------------------------------------------------
// Kernel B: TF32 tensor-core GEMM, 128x128x16 tiles, 3-stage cp.async,
// fused rank-16 + mag/bias epilogue on mma fragments.
// ---------------------------------------------------------------------------
__global__ __launch_bounds__(256, 2)
void dora_tf32_kernel(const float* __restrict__ x,
                      const float* __restrict__ wd,
                      const float* __restrict__ mag,
                      const float* __restrict__ loraB,
                      const float* __restrict__ bias,
                      const float* __restrict__ t,
                      float* __restrict__ out, int M) {
    __shared__ __align__(16) float smem[STAGES * 4096];  // per stage: As[128*16] + Bs[128*16]

    const int tid   = threadIdx.x;
    const int lane  = tid & 31;
    const int warp  = tid >> 5;
    const int warpM = warp >> 2;   // 0..1 -> m offset 64*warpM
    const int warpN = warp & 3;    // 0..3 -> n offset 32*warpN
    const int bm = blockIdx.y * BM;
    const int bn = blockIdx.x * BN;

    float acc[4][4][4];
#pragma unroll
    for (int i = 0; i < 4; i++)
#pragma unroll
        for (int j = 0; j < 4; j++)
#pragma unroll
            for (int k = 0; k < 4; k++) acc[i][j][k] = 0.f;

    // cp.async mapping: 512 float4 per tile, 2 per thread (rows r0 and r0+64)
    const int r0 = tid >> 2;       // 0..63
    const int c4 = tid & 3;        // float4 column within BK=16

    auto issue_loads = [&](int s, int k0) {
        float* As = smem + s * 4096;
        float* Bs = As + 2048;
#pragma unroll
        for (int h = 0; h < 2; h++) {
            int row = r0 + h * 64;
            int sw  = c4 ^ ((row >> 1) & 3);
            uint32_t dA = smem_u32(As + row * 16 + sw * 4);
            const float* sA = x + (size_t)(bm + row) * IN_F + k0 + c4 * 4;
            cp_async16(dA, sA, (bm + row) < M ? 16 : 0);
            uint32_t dB = smem_u32(Bs + row * 16 + sw * 4);
            const float* sB = wd + (size_t)(bn + row) * IN_F + k0 + c4 * 4;
            cp_async16(dB, sB, 16);
        }
    };

    issue_loads(0, 0);  cp_commit();
    issue_loads(1, BK); cp_commit();

    const int arow = warpM * 64 + (lane >> 2);
    const int brow = warpN * 32 + (lane >> 2);
    const int kq   = lane & 3;

    int sc = 0, sw_st = 2;
    for (int it = 0; it < IN_F / BK; ++it) {
        cp_wait<1>();
        __syncthreads();
        const float* As = smem + sc * 4096;
        const float* Bs = As + 2048;

#pragma unroll
        for (int kk = 0; kk < 2; kk++) {
            const int kb = kk * 8 + kq;
            uint32_t a[4][4], b[4][2];
#pragma unroll
            for (int mi = 0; mi < 4; mi++) {
                int r = arow + mi * 16;
                a[mi][0] = f2tf32(As[sw_addr(r,     kb)]);
                a[mi][1] = f2tf32(As[sw_addr(r + 8, kb)]);
                a[mi][2] = f2tf32(As[sw_addr(r,     kb + 4)]);
                a[mi][3] = f2tf32(As[sw_addr(r + 8, kb + 4)]);
            }
#pragma unroll
            for (int ni = 0; ni < 4; ni++) {
                int o = brow + ni * 8;
                b[ni][0] = f2tf32(Bs[sw_addr(o, kb)]);
                b[ni][1] = f2tf32(Bs[sw_addr(o, kb + 4)]);
            }
#pragma unroll
            for (int mi = 0; mi < 4; mi++)
#pragma unroll
                for (int ni = 0; ni < 4; ni++)
                    asm volatile(
                        "mma.sync.aligned.m16n8k8.row.col.f32.tf32.tf32.f32 "
                        "{%0,%1,%2,%3}, {%4,%5,%6,%7}, {%8,%9}, {%0,%1,%2,%3};"
                        : "+f"(acc[mi][ni][0]), "+f"(acc[mi][ni][1]),
                          "+f"(acc[mi][ni][2]), "+f"(acc[mi][ni][3])
                        : "r"(a[mi][0]), "r"(a[mi][1]), "r"(a[mi][2]), "r"(a[mi][3]),
                          "r"(b[ni][0]), "r"(b[ni][1]));
        }

        int kn = (it + 2) * BK;
        if (kn < IN_F) issue_loads(sw_st, kn);
        cp_commit();
        sc = (sc + 1) == STAGES ? 0 : sc + 1;
        sw_st = (sw_st + 1) == STAGES ? 0 : sw_st + 1;
    }

    // ---------------- epilogue: + t @ B^T, then *mag + bias ----------------
    __syncthreads();
    float* ts = smem;          // [128][17]
    float* bs = smem + 2176;   // [128][17]
    for (int i = tid; i < BM * RANK; i += 256) {
        int ml = i >> 4, r = i & 15;
        int mg = bm + ml;
        ts[ml * 17 + r] = (mg < M) ? t[mg * RANK + r] : 0.f;
    }
    for (int i = tid; i < BN * RANK; i += 256) {
        int ol = i >> 4, r = i & 15;
        bs[ol * 17 + r] = loraB[(size_t)(bn + ol) * RANK + r];
    }
    __syncthreads();

    const int mrow = warpM * 64 + (lane >> 2);      // local m base
    const int ocol = warpN * 32 + 2 * (lane & 3);   // local n base

#pragma unroll
    for (int r = 0; r < RANK; r++) {
        float ta[4][2], tb[4][2];
#pragma unroll
        for (int mi = 0; mi < 4; mi++) {
            ta[mi][0] = ts[(mrow + mi * 16) * 17 + r];
            ta[mi][1] = ts[(mrow + mi * 16 + 8) * 17 + r];
        }
#pragma unroll
        for (int ni = 0; ni < 4; ni++) {
            tb[ni][0] = bs[(ocol + ni * 8) * 17 + r];
            tb[ni][1] = bs[(ocol + ni * 8 + 1) * 17 + r];
        }
#pragma unroll
        for (int mi = 0; mi < 4; mi++)
#pragma unroll
            for (int ni = 0; ni < 4; ni++) {
                acc[mi][ni][0] += ta[mi][0] * tb[ni][0];
                acc[mi][ni][1] += ta[mi][0] * tb[ni][1];
                acc[mi][ni][2] += ta[mi][1] * tb[ni][0];
                acc[mi][ni][3] += ta[mi][1] * tb[ni][1];
            }
    }

#pragma unroll
    for (int ni = 0; ni < 4; ni++) {
        int o = bn + ocol + ni * 8;
        float mg0 = mag[o],  mg1 = mag[o + 1];
        float bi0 = bias[o], bi1 = bias[o + 1];
#pragma unroll
        for (int mi = 0; mi < 4; mi++)
#pragma unroll
            for (int h = 0; h < 2; h++) {
                int m = bm + mrow + mi * 16 + 8 * h;
                if (m < M) {
                    float2 v;
                    v.x = acc[mi][ni][2 * h + 0] * mg0 + bi0;
                    v.y = acc[mi][ni][2 * h + 1] * mg1 + bi1;
                    *(float2*)(out + (size_t)m * OUT_F + o) = v;
                }
            }
    }
}

extern "C" void kernel_launch(void* const* d_in, const int* in_sizes, int n_in,
                              void* d_out, int out_size) {
    const float* x     = (const float*)d_in[0];
    const float* wd    = (const float*)d_in[1];
    const float* mag   = (const float*)d_in[2];
    const float* loraA = (const float*)d_in[3];
    const float* loraB = (const float*)d_in[4];
    const float* bias  = (const float*)d_in[5];
    float* out = (float*)d_out;

    const int M = in_sizes[0] / IN_F;

    float* t;
    cudaGetSymbolAddress((void**)&t, g_t);

    lora_t_kernel<<<(M + 31) / 32, 256>>>(x, loraA, t, M);

    dim3 grid(OUT_F / BN, (M + BM - 1) / BM);
    dora_tf32_kernel<<<grid, 256>>>(x, wd, mag, loraB, bias, t, out, M);
}

// round 3
// speedup vs baseline: 3.4061x; 1.3921x over previous
#include <cuda_runtime.h>
#include <cuda_bf16.h>
#include <cstdint>

// y = (x @ Wd^T + s*(x @ A^T) @ B^T) * mag + bias
// x: [M,1024], Wd: [4096,1024], mag: [4096,1], A: [16,1024], B: [4096,16], bias: [4096]

#define IN_F   1024
#define OUT_F  4096
#define RANK   16
#define LORA_SCALE 0.8f

#define BM 128
#define BN 128
#define BK 16
#define STAGES 3

__device__ float g_t[65536];                       // t = s*(x @ A^T)
__device__ __align__(16) float g_x[2048 * IN_F];   // tf32-rounded x
__device__ __align__(16) float g_wd[OUT_F * IN_F]; // tf32-rounded Wd

// ---------------------------------------------------------------------------
// helpers
// ---------------------------------------------------------------------------
__device__ __forceinline__ uint32_t smem_u32(const void* p) {
    return (uint32_t)__cvta_generic_to_shared(p);
}
__device__ __forceinline__ void cp_async16(uint32_t dst, const void* src, int src_bytes) {
    asm volatile("cp.async.cg.shared.global [%0], [%1], 16, %2;\n"
                 :: "r"(dst), "l"(src), "r"(src_bytes));
}
__device__ __forceinline__ void cp_commit() { asm volatile("cp.async.commit_group;\n"); }
template <int N>
__device__ __forceinline__ void cp_wait() { asm volatile("cp.async.wait_group %0;\n" :: "n"(N)); }

__device__ __forceinline__ float f2tf32f(float f) {
    uint32_t r;
    asm("cvt.rna.tf32.f32 %0, %1;" : "=r"(r) : "f"(f));
    return __uint_as_float(r);
}
__device__ __forceinline__ void ldsm_x4(uint32_t& r0, uint32_t& r1, uint32_t& r2, uint32_t& r3,
                                        uint32_t addr) {
    asm volatile("ldmatrix.sync.aligned.m8n8.x4.shared.b16 {%0,%1,%2,%3}, [%4];"
                 : "=r"(r0), "=r"(r1), "=r"(r2), "=r"(r3) : "r"(addr));
}

// ---------------------------------------------------------------------------
// pre-convert fp32 -> tf32-rounded fp32 (vectorized)
// ---------------------------------------------------------------------------
__global__ void cvt_tf32_kernel(const float* __restrict__ in, float* __restrict__ out, int n4) {
    int i = blockIdx.x * blockDim.x + threadIdx.x;
    if (i < n4) {
        float4 v = ((const float4*)in)[i];
        v.x = f2tf32f(v.x); v.y = f2tf32f(v.y); v.z = f2tf32f(v.z); v.w = f2tf32f(v.w);
        ((float4*)out)[i] = v;
    }
}

// ---------------------------------------------------------------------------
// Kernel A: t[m,r] = LORA_SCALE * sum_k x[m,k]*A[r,k]  (full fp32)
// ---------------------------------------------------------------------------
__global__ void lora_t_kernel(const float* __restrict__ x,
                              const float* __restrict__ loraA,
                              float* __restrict__ t, int M) {
    const int tx = threadIdx.x & 15;   // rank
    const int ty = threadIdx.x >> 4;
    const int m0 = blockIdx.x * 32 + ty * 2;
    const bool v0 = m0 < M, v1 = (m0 + 1) < M;

    const float* ar = loraA + (size_t)tx * IN_F;
    const float* x0 = x + (size_t)m0 * IN_F;
    const float* x1 = x0 + IN_F;

    float s00 = 0.f, s01 = 0.f, s10 = 0.f, s11 = 0.f;
    for (int k = 0; k < IN_F; k += 4) {
        float4 a4 = *(const float4*)(ar + k);
        float4 p0 = v0 ? *(const float4*)(x0 + k) : make_float4(0,0,0,0);
        float4 p1 = v1 ? *(const float4*)(x1 + k) : make_float4(0,0,0,0);
        s00 += a4.x * p0.x + a4.y * p0.y;
        s01 += a4.z * p0.z + a4.w * p0.w;
        s10 += a4.x * p1.x + a4.y * p1.y;
        s11 += a4.z * p1.z + a4.w * p1.w;
    }
    if (v0) t[m0 * RANK + tx]       = (s00 + s01) * LORA_SCALE;
    if (v1) t[(m0 + 1) * RANK + tx] = (s10 + s11) * LORA_SCALE;
}

// ---------------------------------------------------------------------------
// Kernel B: TF32 tensor-core GEMM, ldmatrix fragment loads, 3-stage cp.async,
// fused rank-16 + mag/bias epilogue on mma fragments.
// ---------------------------------------------------------------------------
__global__ __launch_bounds__(256, 2)
void dora_tf32_kernel(const float* __restrict__ x,
                      const float* __restrict__ wd,
                      const float* __restrict__ mag,
                      const float* __restrict__ loraB,
                      const float* __restrict__ bias,
                      const float* __restrict__ t,
                      float* __restrict__ out, int M) {
    __shared__ __align__(16) float smem[STAGES * 4096];  // per stage: As[128*16]+Bs[128*16]

    const int tid   = threadIdx.x;
    const int lane  = tid & 31;
    const int warp  = tid >> 5;
    const int warpM = warp >> 2;   // 0..1
    const int warpN = warp & 3;    // 0..3
    const int bm = blockIdx.y * BM;
    const int bn = blockIdx.x * BN;

    float acc[4][4][4];
#pragma unroll
    for (int i = 0; i < 4; i++)
#pragma unroll
        for (int j = 0; j < 4; j++)
#pragma unroll
            for (int k = 0; k < 4; k++) acc[i][j][k] = 0.f;

    // cp.async mapping: 512 float4 per tile, 2 per thread (rows r0 and r0+64)
    const int r0 = tid >> 2;
    const int c4 = tid & 3;

    auto issue_loads = [&](int s, int k0) {
        float* As = smem + s * 4096;
        float* Bs = As + 2048;
#pragma unroll
        for (int h = 0; h < 2; h++) {
            int row = r0 + h * 64;
            int sw  = c4 ^ ((row >> 1) & 3);
            uint32_t dA = smem_u32(As + row * 16 + sw * 4);
            const float* sA = x + (size_t)(bm + row) * IN_F + k0 + c4 * 4;
            cp_async16(dA, sA, (bm + row) < M ? 16 : 0);
            uint32_t dB = smem_u32(Bs + row * 16 + sw * 4);
            const float* sB = wd + (size_t)(bn + row) * IN_F + k0 + c4 * 4;
            cp_async16(dB, sB, 16);
        }
    };

    issue_loads(0, 0);  cp_commit();
    issue_loads(1, BK); cp_commit();

    // ------- precompute ldmatrix byte offsets (within a stage) -------
    // ldmatrix x4: lanes g=lane>>3 supply row addresses for matrix g; r=lane&7.
    const int lg = lane >> 3, lr = lane & 7;

    uint32_t offA[2][4];  // [kk][mi]
#pragma unroll
    for (int kk = 0; kk < 2; kk++)
#pragma unroll
        for (int mi = 0; mi < 4; mi++) {
            int row = warpM * 64 + mi * 16 + (lg & 1) * 8 + lr;
            int grp = 2 * kk + (lg >> 1);
            offA[kk][mi] = (uint32_t)((row * 16 + ((grp ^ ((row >> 1) & 3)) << 2)) * 4);
        }
    uint32_t offB[2][2];  // [kk][ni-pair]
#pragma unroll
    for (int kk = 0; kk < 2; kk++)
#pragma unroll
        for (int np = 0; np < 2; np++) {
            int row = warpN * 32 + np * 16 + (lg >> 1) * 8 + lr;
            int grp = 2 * kk + (lg & 1);
            offB[kk][np] = (uint32_t)(8192 + (row * 16 + ((grp ^ ((row >> 1) & 3)) << 2)) * 4);
        }

    const uint32_t sbase = smem_u32(smem);

    int sc = 0, sw_st = 2;
    for (int it = 0; it < IN_F / BK; ++it) {
        cp_wait<1>();
        __syncthreads();
        const uint32_t stage = sbase + sc * 16384;

#pragma unroll
        for (int kk = 0; kk < 2; kk++) {
            uint32_t a[4][4], b[4][2];
#pragma unroll
            for (int mi = 0; mi < 4; mi++)
                ldsm_x4(a[mi][0], a[mi][1], a[mi][2], a[mi][3], stage + offA[kk][mi]);
#pragma unroll
            for (int np = 0; np < 2; np++)
                ldsm_x4(b[2*np][0], b[2*np][1], b[2*np+1][0], b[2*np+1][1],
                        stage + offB[kk][np]);
#pragma unroll
            for (int mi = 0; mi < 4; mi++)
#pragma unroll
                for (int ni = 0; ni < 4; ni++)
                    asm volatile(
                        "mma.sync.aligned.m16n8k8.row.col.f32.tf32.tf32.f32 "
                        "{%0,%1,%2,%3}, {%4,%5,%6,%7}, {%8,%9}, {%0,%1,%2,%3};"
                        : "+f"(acc[mi][ni][0]), "+f"(acc[mi][ni][1]),
                          "+f"(acc[mi][ni][2]), "+f"(acc[mi][ni][3])
                        : "r"(a[mi][0]), "r"(a[mi][1]), "r"(a[mi][2]), "r"(a[mi][3]),
                          "r"(b[ni][0]), "r"(b[ni][1]));
        }

        int kn = (it + 2) * BK;
        if (kn < IN_F) issue_loads(sw_st, kn);
        cp_commit();
        sc = (sc + 1) == STAGES ? 0 : sc + 1;
        sw_st = (sw_st + 1) == STAGES ? 0 : sw_st + 1;
    }

    // ---------------- epilogue: + t @ B^T, then *mag + bias ----------------
    __syncthreads();
    float* ts = smem;          // [128][17]
    float* bs = smem + 2176;   // [128][17]
    for (int i = tid; i < BM * RANK; i += 256) {
        int ml = i >> 4, r = i & 15;
        int mg = bm + ml;
        ts[ml * 17 + r] = (mg < M) ? t[mg * RANK + r] : 0.f;
    }
    for (int i = tid; i < BN * RANK; i += 256) {
        int ol = i >> 4, r = i & 15;
        bs[ol * 17 + r] = loraB[(size_t)(bn + ol) * RANK + r];
    }
    __syncthreads();

    const int mrow = warpM * 64 + (lane >> 2);
    const int ocol = warpN * 32 + 2 * (lane & 3);

#pragma unroll
    for (int r = 0; r < RANK; r++) {
        float ta[4][2], tb[4][2];
#pragma unroll
        for (int mi = 0; mi < 4; mi++) {
            ta[mi][0] = ts[(mrow + mi * 16) * 17 + r];
            ta[mi][1] = ts[(mrow + mi * 16 + 8) * 17 + r];
        }
#pragma unroll
        for (int ni = 0; ni < 4; ni++) {
            tb[ni][0] = bs[(ocol + ni * 8) * 17 + r];
            tb[ni][1] = bs[(ocol + ni * 8 + 1) * 17 + r];
        }
#pragma unroll
        for (int mi = 0; mi < 4; mi++)
#pragma unroll
            for (int ni = 0; ni < 4; ni++) {
                acc[mi][ni][0] += ta[mi][0] * tb[ni][0];
                acc[mi][ni][1] += ta[mi][0] * tb[ni][1];
                acc[mi][ni][2] += ta[mi][1] * tb[ni][0];
                acc[mi][ni][3] += ta[mi][1] * tb[ni][1];
            }
    }

#pragma unroll
    for (int ni = 0; ni < 4; ni++) {
        int o = bn + ocol + ni * 8;
        float mg0 = mag[o],  mg1 = mag[o + 1];
        float bi0 = bias[o], bi1 = bias[o + 1];
#pragma unroll
        for (int mi = 0; mi < 4; mi++)
#pragma unroll
            for (int h = 0; h < 2; h++) {
                int m = bm + mrow + mi * 16 + 8 * h;
                if (m < M) {
                    float2 v;
                    v.x = acc[mi][ni][2 * h + 0] * mg0 + bi0;
                    v.y = acc[mi][ni][2 * h + 1] * mg1 + bi1;
                    *(float2*)(out + (size_t)m * OUT_F + o) = v;
                }
            }
    }
}

extern "C" void kernel_launch(void* const* d_in, const int* in_sizes, int n_in,
                              void* d_out, int out_size) {
    const float* x     = (const float*)d_in[0];
    const float* wd    = (const float*)d_in[1];
    const float* mag   = (const float*)d_in[2];
    const float* loraA = (const float*)d_in[3];
    const float* loraB = (const float*)d_in[4];
    const float* bias  = (const float*)d_in[5];
    float* out = (float*)d_out;

    const int M = in_sizes[0] / IN_F;

    float *t, *xc, *wc;
    cudaGetSymbolAddress((void**)&t, g_t);
    cudaGetSymbolAddress((void**)&xc, g_x);
    cudaGetSymbolAddress((void**)&wc, g_wd);

    int nx4 = (M * IN_F) / 4;
    int nw4 = (OUT_F * IN_F) / 4;
    cvt_tf32_kernel<<<(nw4 + 255) / 256, 256>>>(wd, wc, nw4);
    cvt_tf32_kernel<<<(nx4 + 255) / 256, 256>>>(x, xc, nx4);
    lora_t_kernel<<<(M + 31) / 32, 256>>>(x, loraA, t, M);

    dim3 grid(OUT_F / BN, (M + BM - 1) / BM);
    dora_tf32_kernel<<<grid, 256>>>(xc, wc, mag, loraB, bias, t, out, M);
}

// round 5
// speedup vs baseline: 4.6799x; 1.3740x over previous
#include <cuda_runtime.h>
#include <cuda_fp16.h>
#include <cstdint>

// y = (x @ Wd^T + s*(x @ A^T) @ B^T) * mag + bias
// K-fusion: A = [fp16(x) | fp16(t) | 0]  (K_TOT=1088),
//           B = [fp16(Wd) | fp16(loraB) | 0]
// -> one fp16 GEMM (fp32 accum), epilogue = *mag + bias.

#define IN_F   1024
#define OUT_F  4096
#define RANK   16
#define LORA_SCALE 0.8f

#define K_TOT  1088           // 17 * 64
#define BK     64             // halves per iter (128 bytes/row)
#define NITER  17
#define STAGES 3
#define BM     128
#define BN     128
#define STAGE_BYTES 32768     // A 16KB + B 16KB
#define SMEM_BYTES (STAGES * STAGE_BYTES)

__device__ __align__(16) __half g_xcat[2048 * K_TOT];
__device__ __align__(16) __half g_wcat[OUT_F * K_TOT];

// ---------------------------------------------------------------------------
// helpers
// ---------------------------------------------------------------------------
__device__ __forceinline__ uint32_t smem_u32(const void* p) {
    return (uint32_t)__cvta_generic_to_shared(p);
}
__device__ __forceinline__ void cp_async16(uint32_t dst, const void* src, int src_bytes) {
    asm volatile("cp.async.cg.shared.global [%0], [%1], 16, %2;\n"
                 :: "r"(dst), "l"(src), "r"(src_bytes));
}
__device__ __forceinline__ void cp_commit() { asm volatile("cp.async.commit_group;\n"); }
template <int N>
__device__ __forceinline__ void cp_wait() { asm volatile("cp.async.wait_group %0;\n" :: "n"(N)); }

__device__ __forceinline__ void ldsm_x4(uint32_t& r0, uint32_t& r1, uint32_t& r2, uint32_t& r3,
                                        uint32_t addr) {
    asm volatile("ldmatrix.sync.aligned.m8n8.x4.shared.b16 {%0,%1,%2,%3}, [%4];"
                 : "=r"(r0), "=r"(r1), "=r"(r2), "=r"(r3) : "r"(addr));
}

// ---------------------------------------------------------------------------
// preprocessing kernels
// ---------------------------------------------------------------------------
__global__ void pack_fp16_kernel(const float* __restrict__ in, __half* __restrict__ out,
                                 int n4, int cols) {
    int i = blockIdx.x * blockDim.x + threadIdx.x;
    if (i < n4) {
        int row = (i * 4) / cols, col = (i * 4) % cols;
        float4 v = *(const float4*)(in + (size_t)i * 4);
        __half2 h0 = __floats2half2_rn(v.x, v.y);
        __half2 h1 = __floats2half2_rn(v.z, v.w);
        __half* p = out + (size_t)row * K_TOT + col;
        *(__half2*)(p)     = h0;
        *(__half2*)(p + 2) = h1;
    }
}

__global__ void pack_wtail_kernel(const float* __restrict__ loraB, __half* __restrict__ wcat) {
    int i = blockIdx.x * blockDim.x + threadIdx.x;  // 4096*64
    int row = i >> 6, col = i & 63;
    __half v = (col < RANK) ? __float2half(loraB[row * RANK + col]) : __half(0.f);
    wcat[(size_t)row * K_TOT + 1024 + col] = v;
}

// t[m,r] = LORA_SCALE * sum_k x[m,k]*A[r,k] (fp32 math), packed into xcat tail
__global__ void lora_t_kernel(const float* __restrict__ x,
                              const float* __restrict__ loraA,
                              __half* __restrict__ xcat, int M) {
    const int tx = threadIdx.x & 15;   // rank
    const int ty = threadIdx.x >> 4;
    const int m0 = blockIdx.x * 32 + ty * 2;
    const bool v0 = m0 < M, v1 = (m0 + 1) < M;

    const float* ar = loraA + (size_t)tx * IN_F;
    const float* x0 = x + (size_t)m0 * IN_F;
    const float* x1 = x0 + IN_F;

    float s00 = 0.f, s01 = 0.f, s10 = 0.f, s11 = 0.f;
    for (int k = 0; k < IN_F; k += 4) {
        float4 a4 = *(const float4*)(ar + k);
        float4 p0 = v0 ? *(const float4*)(x0 + k) : make_float4(0,0,0,0);
        float4 p1 = v1 ? *(const float4*)(x1 + k) : make_float4(0,0,0,0);
        s00 += a4.x * p0.x + a4.y * p0.y;
        s01 += a4.z * p0.z + a4.w * p0.w;
        s10 += a4.x * p1.x + a4.y * p1.y;
        s11 += a4.z * p1.z + a4.w * p1.w;
    }
    if (v0) xcat[(size_t)m0 * K_TOT + 1024 + tx] = __float2half((s00 + s01) * LORA_SCALE);
    if (v1) xcat[(size_t)(m0 + 1) * K_TOT + 1024 + tx] = __float2half((s10 + s11) * LORA_SCALE);
#pragma unroll
    for (int q = 0; q < 3; q++) {
        if (v0) xcat[(size_t)m0 * K_TOT + 1040 + tx * 3 + q] = __half(0.f);
        if (v1) xcat[(size_t)(m0 + 1) * K_TOT + 1040 + tx * 3 + q] = __half(0.f);
    }
}

// ---------------------------------------------------------------------------
// main GEMM: fp16 mma.m16n8k16, 128x128x64 tiles, 3-stage cp.async
// ---------------------------------------------------------------------------
__global__ __launch_bounds__(256, 2)
void dora_f16_kernel(const __half* __restrict__ xcat,
                     const __half* __restrict__ wcat,
                     const float* __restrict__ mag,
                     const float* __restrict__ bias,
                     float* __restrict__ out, int M) {
    extern __shared__ __align__(1024) char smraw[];

    const int tid   = threadIdx.x;
    const int lane  = tid & 31;
    const int warp  = tid >> 5;
    const int warpM = warp >> 2;   // 0..1 -> m offset 64*warpM
    const int warpN = warp & 3;    // 0..3 -> n offset 32*warpN
    const int bm = blockIdx.y * BM;
    const int bn = blockIdx.x * BN;

    float acc[4][4][4];
#pragma unroll
    for (int i = 0; i < 4; i++)
#pragma unroll
        for (int j = 0; j < 4; j++)
#pragma unroll
            for (int k = 0; k < 4; k++) acc[i][j][k] = 0.f;

    // cp.async: A 1024 chunks + B 1024 chunks per stage; 4+4 per thread
    const int ldr = tid >> 1;            // 0..127 row
    const int ldc = (tid & 1) * 4;       // chunk group 0 or 4

    auto load_stage = [&](int s, int it) {
        uint32_t st = smem_u32(smraw) + s * STAGE_BYTES;
        const int kb = it * 128;  // byte offset in row
        const __half* xrow = xcat + (size_t)(bm + ldr) * K_TOT;
        const __half* wrow = wcat + (size_t)(bn + ldr) * K_TOT;
        int xbytes = (bm + ldr) < M ? 16 : 0;
#pragma unroll
        for (int j = 0; j < 4; j++) {
            int c = ldc + j;
            uint32_t dst = st + (uint32_t)(ldr * 128 + (((c ^ (ldr & 7)) << 4)));
            cp_async16(dst, (const char*)xrow + kb + c * 16, xbytes);
            uint32_t dstB = dst + 16384;
            cp_async16(dstB, (const char*)wrow + kb + c * 16, 16);
        }
    };

    load_stage(0, 0); cp_commit();
    load_stage(1, 1); cp_commit();

    // ---- ldmatrix offsets for k-step 0; other ksteps XOR (kk*32) ----
    const int lg = lane >> 3, lr = lane & 7;

    uint32_t offA[4];   // per m-tile
#pragma unroll
    for (int mi = 0; mi < 4; mi++) {
        int row = warpM * 64 + mi * 16 + (lg & 1) * 8 + lr;
        int grp = lg >> 1;                               // byte-col group 0/1
        offA[mi] = (uint32_t)(row * 128 + (((grp ^ (row & 7)) << 4)));
    }
    uint32_t offB[2];   // per n-tile pair
#pragma unroll
    for (int np = 0; np < 2; np++) {
        int row = warpN * 32 + np * 16 + (lg >> 1) * 8 + lr;
        int grp = lg & 1;
        offB[np] = (uint32_t)(16384 + row * 128 + (((grp ^ (row & 7)) << 4)));
    }

    const uint32_t sbase = smem_u32(smraw);

    int sc = 0, sl = 2;
    for (int it = 0; it < NITER; ++it) {
        cp_wait<1>();
        __syncthreads();
        const uint32_t stage = sbase + sc * STAGE_BYTES;

#pragma unroll
        for (int kk = 0; kk < 4; kk++) {
            const uint32_t kx = (uint32_t)(kk * 32);
            uint32_t a[4][4], b[4][2];
#pragma unroll
            for (int mi = 0; mi < 4; mi++)
                ldsm_x4(a[mi][0], a[mi][1], a[mi][2], a[mi][3],
                        stage + (offA[mi] ^ kx));
#pragma unroll
            for (int np = 0; np < 2; np++)
                ldsm_x4(b[2*np][0], b[2*np][1], b[2*np+1][0], b[2*np+1][1],
                        stage + (offB[np] ^ kx));
#pragma unroll
            for (int mi = 0; mi < 4; mi++)
#pragma unroll
                for (int ni = 0; ni < 4; ni++)
                    asm volatile(
                        "mma.sync.aligned.m16n8k16.row.col.f32.f16.f16.f32 "
                        "{%0,%1,%2,%3}, {%4,%5,%6,%7}, {%8,%9}, {%0,%1,%2,%3};"
                        : "+f"(acc[mi][ni][0]), "+f"(acc[mi][ni][1]),
                          "+f"(acc[mi][ni][2]), "+f"(acc[mi][ni][3])
                        : "r"(a[mi][0]), "r"(a[mi][1]), "r"(a[mi][2]), "r"(a[mi][3]),
                          "r"(b[ni][0]), "r"(b[ni][1]));
        }

        int jn = it + 2;
        if (jn < NITER) load_stage(sl, jn);
        cp_commit();
        sc = (sc + 1) == STAGES ? 0 : sc + 1;
        sl = (sl + 1) == STAGES ? 0 : sl + 1;
    }

    // ---------------- epilogue: *mag + bias, store ----------------
    __syncthreads();
    float* magS  = (float*)smraw;
    float* biasS = magS + BN;
    if (tid < BN) { magS[tid] = mag[bn + tid]; biasS[tid] = bias[bn + tid]; }
    __syncthreads();

    const int mrow = warpM * 64 + (lane >> 2);
    const int ocol = warpN * 32 + 2 * (lane & 3);

#pragma unroll
    for (int ni = 0; ni < 4; ni++) {
        int ol = ocol + ni * 8;
        float mg0 = magS[ol],  mg1 = magS[ol + 1];
        float bi0 = biasS[ol], bi1 = biasS[ol + 1];
#pragma unroll
        for (int mi = 0; mi < 4; mi++)
#pragma unroll
            for (int h = 0; h < 2; h++) {
                int m = bm + mrow + mi * 16 + 8 * h;
                if (m < M) {
                    float2 v;
                    v.x = acc[mi][ni][2 * h + 0] * mg0 + bi0;
                    v.y = acc[mi][ni][2 * h + 1] * mg1 + bi1;
                    *(float2*)(out + (size_t)m * OUT_F + bn + ol) = v;
                }
            }
    }
}

extern "C" void kernel_launch(void* const* d_in, const int* in_sizes, int n_in,
                              void* d_out, int out_size) {
    const float* x     = (const float*)d_in[0];
    const float* wd    = (const float*)d_in[1];
    const float* mag   = (const float*)d_in[2];
    const float* loraA = (const float*)d_in[3];
    const float* loraB = (const float*)d_in[4];
    const float* bias  = (const float*)d_in[5];
    float* out = (float*)d_out;

    const int M = in_sizes[0] / IN_F;

    __half *xcat, *wcat;
    cudaGetSymbolAddress((void**)&xcat, g_xcat);
    cudaGetSymbolAddress((void**)&wcat, g_wcat);

    int nx4 = (M * IN_F) / 4;
    int nw4 = (OUT_F * IN_F) / 4;
    pack_fp16_kernel<<<(nw4 + 255) / 256, 256>>>(wd, wcat, nw4, IN_F);
    pack_fp16_kernel<<<(nx4 + 255) / 256, 256>>>(x, xcat, nx4, IN_F);
    pack_wtail_kernel<<<(OUT_F * 64) / 256, 256>>>(loraB, wcat);
    lora_t_kernel<<<(M + 31) / 32, 256>>>(x, loraA, xcat, M);

    static int smem_set = 0;
    if (!smem_set) {
        cudaFuncSetAttribute(dora_f16_kernel,
                             cudaFuncAttributeMaxDynamicSharedMemorySize, SMEM_BYTES);
        smem_set = 1;
    }
    dim3 grid(OUT_F / BN, (M + BM - 1) / BM);
    dora_f16_kernel<<<grid, 256, SMEM_BYTES>>>(xcat, wcat, mag, bias, out, M);
}

// round 6
// speedup vs baseline: 6.2433x; 1.3341x over previous
#include <cuda_runtime.h>
#include <cuda_fp16.h>
#include <cstdint>

// y = (x @ Wd^T + s*(x @ A^T) @ B^T) * mag + bias
// K-fusion: A = [fp16(x) | fp16(t) | 0]  (K_TOT=1088),
//           B = [fp16(Wd) | fp16(loraB) | 0]
// -> one fp16 GEMM (fp32 accum), epilogue = *mag + bias.

#define IN_F   1024
#define OUT_F  4096
#define RANK   16
#define LORA_SCALE 0.8f

#define K_TOT  1088           // 17 * 64
#define NITER  17
#define STAGES 3
#define BM     128
#define BN     128
#define STAGE_BYTES 32768     // A 16KB + B 16KB
#define SMEM_BYTES (STAGES * STAGE_BYTES)

#define KSPLIT 8              // lora split-K factor (1024/128)

__device__ __align__(16) __half g_xcat[2048 * K_TOT];
__device__ __align__(16) __half g_wcat[OUT_F * K_TOT];
__device__ __align__(16) float  g_tp[KSPLIT * 2048 * RANK];

// ---------------------------------------------------------------------------
// helpers
// ---------------------------------------------------------------------------
__device__ __forceinline__ uint32_t smem_u32(const void* p) {
    return (uint32_t)__cvta_generic_to_shared(p);
}
__device__ __forceinline__ void cp_async16(uint32_t dst, const void* src, int src_bytes) {
    asm volatile("cp.async.cg.shared.global [%0], [%1], 16, %2;\n"
                 :: "r"(dst), "l"(src), "r"(src_bytes));
}
__device__ __forceinline__ void cp_commit() { asm volatile("cp.async.commit_group;\n"); }
template <int N>
__device__ __forceinline__ void cp_wait() { asm volatile("cp.async.wait_group %0;\n" :: "n"(N)); }

__device__ __forceinline__ void ldsm_x4(uint32_t& r0, uint32_t& r1, uint32_t& r2, uint32_t& r3,
                                        uint32_t addr) {
    asm volatile("ldmatrix.sync.aligned.m8n8.x4.shared.b16 {%0,%1,%2,%3}, [%4];"
                 : "=r"(r0), "=r"(r1), "=r"(r2), "=r"(r3) : "r"(addr));
}

// ---------------------------------------------------------------------------
// preprocessing kernels
// ---------------------------------------------------------------------------
__global__ void pack_fp16_kernel(const float* __restrict__ in, __half* __restrict__ out,
                                 int n4, int cols) {
    int i = blockIdx.x * blockDim.x + threadIdx.x;
    if (i < n4) {
        int row = (i * 4) / cols, col = (i * 4) % cols;
        float4 v = *(const float4*)(in + (size_t)i * 4);
        __half2 h0 = __floats2half2_rn(v.x, v.y);
        __half2 h1 = __floats2half2_rn(v.z, v.w);
        __half* p = out + (size_t)row * K_TOT + col;
        *(__half2*)(p)     = h0;
        *(__half2*)(p + 2) = h1;
    }
}

__global__ void pack_wtail_kernel(const float* __restrict__ loraB, __half* __restrict__ wcat) {
    int i = blockIdx.x * blockDim.x + threadIdx.x;  // 4096*64
    int row = i >> 6, col = i & 63;
    __half v = (col < RANK) ? __float2half(loraB[row * RANK + col]) : __half(0.f);
    wcat[(size_t)row * K_TOT + 1024 + col] = v;
}

// split-K partial: tp[kc][m][r] = sum_{k in slice kc} x[m,k]*A[r,k]
__global__ void lora_part_kernel(const float* __restrict__ x,
                                 const float* __restrict__ loraA,
                                 float* __restrict__ tp, int M) {
    const int tx = threadIdx.x & 15;   // rank
    const int ty = threadIdx.x >> 4;
    const int m0 = blockIdx.x * 32 + ty * 2;
    const int kc = blockIdx.y;
    const int k0 = kc * (IN_F / KSPLIT);
    const bool v0 = m0 < M, v1 = (m0 + 1) < M;

    const float* ar = loraA + (size_t)tx * IN_F + k0;
    const float* x0 = x + (size_t)m0 * IN_F + k0;
    const float* x1 = x0 + IN_F;

    float s00 = 0.f, s01 = 0.f, s10 = 0.f, s11 = 0.f;
#pragma unroll 8
    for (int k = 0; k < IN_F / KSPLIT; k += 4) {
        float4 a4 = *(const float4*)(ar + k);
        float4 p0 = v0 ? *(const float4*)(x0 + k) : make_float4(0,0,0,0);
        float4 p1 = v1 ? *(const float4*)(x1 + k) : make_float4(0,0,0,0);
        s00 += a4.x * p0.x + a4.y * p0.y;
        s01 += a4.z * p0.z + a4.w * p0.w;
        s10 += a4.x * p1.x + a4.y * p1.y;
        s11 += a4.z * p1.z + a4.w * p1.w;
    }
    float* dst = tp + (size_t)kc * 2048 * RANK;
    if (v0) dst[m0 * RANK + tx]       = s00 + s01;
    if (v1) dst[(m0 + 1) * RANK + tx] = s10 + s11;
}

// reduce partials -> fp16 tail of xcat (+ zero pad)
__global__ void lora_fin_kernel(const float* __restrict__ tp,
                                __half* __restrict__ xcat, int M) {
    int i = blockIdx.x * blockDim.x + threadIdx.x;
    int m = i >> 4, r = i & 15;
    if (m >= M) return;
    float s = 0.f;
#pragma unroll
    for (int kc = 0; kc < KSPLIT; kc++)
        s += tp[(size_t)kc * 2048 * RANK + m * RANK + r];
    __half* row = xcat + (size_t)m * K_TOT + 1024;
    row[r] = __float2half(s * LORA_SCALE);
#pragma unroll
    for (int q = 0; q < 3; q++) row[16 + r * 3 + q] = __half(0.f);
}

// ---------------------------------------------------------------------------
// main GEMM: fp16 mma.m16n8k16, 128x128x64 tiles, 3-stage cp.async
// ---------------------------------------------------------------------------
__global__ __launch_bounds__(256, 2)
void dora_f16_kernel(const __half* __restrict__ xcat,
                     const __half* __restrict__ wcat,
                     const float* __restrict__ mag,
                     const float* __restrict__ bias,
                     float* __restrict__ out, int M) {
    extern __shared__ __align__(1024) char smraw[];

    const int tid   = threadIdx.x;
    const int lane  = tid & 31;
    const int warp  = tid >> 5;
    const int warpM = warp >> 2;   // 0..1 -> m offset 64*warpM
    const int warpN = warp & 3;    // 0..3 -> n offset 32*warpN
    const int bm = blockIdx.y * BM;
    const int bn = blockIdx.x * BN;

    float acc[4][4][4];
#pragma unroll
    for (int i = 0; i < 4; i++)
#pragma unroll
        for (int j = 0; j < 4; j++)
#pragma unroll
            for (int k = 0; k < 4; k++) acc[i][j][k] = 0.f;

    // cp.async: A 1024 chunks + B 1024 chunks per stage; 4+4 per thread
    const int ldr = tid >> 1;            // 0..127 row
    const int ldc = (tid & 1) * 4;       // chunk group 0 or 4

    auto load_stage = [&](int s, int it) {
        uint32_t st = smem_u32(smraw) + s * STAGE_BYTES;
        const int kb = it * 128;  // byte offset in row
        const __half* xrow = xcat + (size_t)(bm + ldr) * K_TOT;
        const __half* wrow = wcat + (size_t)(bn + ldr) * K_TOT;
        int xbytes = (bm + ldr) < M ? 16 : 0;
#pragma unroll
        for (int j = 0; j < 4; j++) {
            int c = ldc + j;
            uint32_t dst = st + (uint32_t)(ldr * 128 + (((c ^ (ldr & 7)) << 4)));
            cp_async16(dst, (const char*)xrow + kb + c * 16, xbytes);
            uint32_t dstB = dst + 16384;
            cp_async16(dstB, (const char*)wrow + kb + c * 16, 16);
        }
    };

    load_stage(0, 0); cp_commit();
    load_stage(1, 1); cp_commit();

    // ---- ldmatrix offsets for k-step 0; other ksteps XOR (kk*32) ----
    const int lg = lane >> 3, lr = lane & 7;

    uint32_t offA[4];   // per m-tile
#pragma unroll
    for (int mi = 0; mi < 4; mi++) {
        int row = warpM * 64 + mi * 16 + (lg & 1) * 8 + lr;
        int grp = lg >> 1;                               // byte-col group 0/1
        offA[mi] = (uint32_t)(row * 128 + (((grp ^ (row & 7)) << 4)));
    }
    uint32_t offB[2];   // per n-tile pair
#pragma unroll
    for (int np = 0; np < 2; np++) {
        int row = warpN * 32 + np * 16 + (lg >> 1) * 8 + lr;
        int grp = lg & 1;
        offB[np] = (uint32_t)(16384 + row * 128 + (((grp ^ (row & 7)) << 4)));
    }

    const uint32_t sbase = smem_u32(smraw);

    int sc = 0, sl = 2;
    for (int it = 0; it < NITER; ++it) {
        cp_wait<1>();
        __syncthreads();
        const uint32_t stage = sbase + sc * STAGE_BYTES;

#pragma unroll
        for (int kk = 0; kk < 4; kk++) {
            const uint32_t kx = (uint32_t)(kk * 32);
            uint32_t a[4][4], b[4][2];
#pragma unroll
            for (int mi = 0; mi < 4; mi++)
                ldsm_x4(a[mi][0], a[mi][1], a[mi][2], a[mi][3],
                        stage + (offA[mi] ^ kx));
#pragma unroll
            for (int np = 0; np < 2; np++)
                ldsm_x4(b[2*np][0], b[2*np][1], b[2*np+1][0], b[2*np+1][1],
                        stage + (offB[np] ^ kx));
#pragma unroll
            for (int mi = 0; mi < 4; mi++)
#pragma unroll
                for (int ni = 0; ni < 4; ni++)
                    asm volatile(
                        "mma.sync.aligned.m16n8k16.row.col.f32.f16.f16.f32 "
                        "{%0,%1,%2,%3}, {%4,%5,%6,%7}, {%8,%9}, {%0,%1,%2,%3};"
                        : "+f"(acc[mi][ni][0]), "+f"(acc[mi][ni][1]),
                          "+f"(acc[mi][ni][2]), "+f"(acc[mi][ni][3])
                        : "r"(a[mi][0]), "r"(a[mi][1]), "r"(a[mi][2]), "r"(a[mi][3]),
                          "r"(b[ni][0]), "r"(b[ni][1]));
        }

        int jn = it + 2;
        if (jn < NITER) load_stage(sl, jn);
        cp_commit();
        sc = (sc + 1) == STAGES ? 0 : sc + 1;
        sl = (sl + 1) == STAGES ? 0 : sl + 1;
    }

    // ---------------- epilogue: *mag + bias, store ----------------
    __syncthreads();
    float* magS  = (float*)smraw;
    float* biasS = magS + BN;
    if (tid < BN) { magS[tid] = mag[bn + tid]; biasS[tid] = bias[bn + tid]; }
    __syncthreads();

    const int mrow = warpM * 64 + (lane >> 2);
    const int ocol = warpN * 32 + 2 * (lane & 3);

#pragma unroll
    for (int ni = 0; ni < 4; ni++) {
        int ol = ocol + ni * 8;
        float mg0 = magS[ol],  mg1 = magS[ol + 1];
        float bi0 = biasS[ol], bi1 = biasS[ol + 1];
#pragma unroll
        for (int mi = 0; mi < 4; mi++)
#pragma unroll
            for (int h = 0; h < 2; h++) {
                int m = bm + mrow + mi * 16 + 8 * h;
                if (m < M) {
                    float2 v;
                    v.x = acc[mi][ni][2 * h + 0] * mg0 + bi0;
                    v.y = acc[mi][ni][2 * h + 1] * mg1 + bi1;
                    *(float2*)(out + (size_t)m * OUT_F + bn + ol) = v;
                }
            }
    }
}

extern "C" void kernel_launch(void* const* d_in, const int* in_sizes, int n_in,
                              void* d_out, int out_size) {
    const float* x     = (const float*)d_in[0];
    const float* wd    = (const float*)d_in[1];
    const float* mag   = (const float*)d_in[2];
    const float* loraA = (const float*)d_in[3];
    const float* loraB = (const float*)d_in[4];
    const float* bias  = (const float*)d_in[5];
    float* out = (float*)d_out;

    const int M = in_sizes[0] / IN_F;

    __half *xcat, *wcat;
    float* tp;
    cudaGetSymbolAddress((void**)&xcat, g_xcat);
    cudaGetSymbolAddress((void**)&wcat, g_wcat);
    cudaGetSymbolAddress((void**)&tp, g_tp);

    int nx4 = (M * IN_F) / 4;
    int nw4 = (OUT_F * IN_F) / 4;
    pack_fp16_kernel<<<(nw4 + 255) / 256, 256>>>(wd, wcat, nw4, IN_F);
    pack_fp16_kernel<<<(nx4 + 255) / 256, 256>>>(x, xcat, nx4, IN_F);
    pack_wtail_kernel<<<(OUT_F * 64) / 256, 256>>>(loraB, wcat);

    dim3 lgrid((M + 31) / 32, KSPLIT);
    lora_part_kernel<<<lgrid, 256>>>(x, loraA, tp, M);
    lora_fin_kernel<<<(M * RANK + 255) / 256, 256>>>(tp, xcat, M);

    static int smem_set = 0;
    if (!smem_set) {
        cudaFuncSetAttribute(dora_f16_kernel,
                             cudaFuncAttributeMaxDynamicSharedMemorySize, SMEM_BYTES);
        smem_set = 1;
    }
    dim3 grid(OUT_F / BN, (M + BM - 1) / BM);
    dora_f16_kernel<<<grid, 256, SMEM_BYTES>>>(xcat, wcat, mag, bias, out, M);
}

// round 7
// speedup vs baseline: 7.2807x; 1.1662x over previous
#include <cuda_runtime.h>
#include <cuda_fp16.h>
#include <cstdint>

// y = (x @ Wd^T + s*(x @ A^T) @ B^T) * mag + bias
// K-fusion: A = [fp16(x) | fp16(t) | 0]  (K_TOT=1088),
//           B = [fp16(Wd) | fp16(loraB) | 0]
// -> one fp16 GEMM (fp32 accum), epilogue = *mag + bias.

#define IN_F   1024
#define OUT_F  4096
#define RANK   16
#define LORA_SCALE 0.8f

#define K_TOT  1088           // 17 * 64
#define NITER  17
#define STAGES 3
#define BM     128
#define BN     128
#define STAGE_BYTES 32768     // A 16KB + B 16KB
#define SMEM_BYTES (STAGES * STAGE_BYTES)

#define KSPLIT 8              // lora split-K factor (1024/128)
#define LKS    (IN_F / KSPLIT)   // 128 k per slice
#define LROWS  64                // m-rows per lora block
#define XPITCH 132               // padded row pitch (floats) for x smem
#define APITCH 132

__device__ __align__(16) __half g_xcat[2048 * K_TOT];
__device__ __align__(16) __half g_wcat[OUT_F * K_TOT];
__device__ __align__(16) float  g_tp[KSPLIT * 2048 * RANK];

// ---------------------------------------------------------------------------
// helpers
// ---------------------------------------------------------------------------
__device__ __forceinline__ uint32_t smem_u32(const void* p) {
    return (uint32_t)__cvta_generic_to_shared(p);
}
__device__ __forceinline__ void cp_async16(uint32_t dst, const void* src, int src_bytes) {
    asm volatile("cp.async.cg.shared.global [%0], [%1], 16, %2;\n"
                 :: "r"(dst), "l"(src), "r"(src_bytes));
}
__device__ __forceinline__ void cp_commit() { asm volatile("cp.async.commit_group;\n"); }
template <int N>
__device__ __forceinline__ void cp_wait() { asm volatile("cp.async.wait_group %0;\n" :: "n"(N)); }

__device__ __forceinline__ void ldsm_x4(uint32_t& r0, uint32_t& r1, uint32_t& r2, uint32_t& r3,
                                        uint32_t addr) {
    asm volatile("ldmatrix.sync.aligned.m8n8.x4.shared.b16 {%0,%1,%2,%3}, [%4];"
                 : "=r"(r0), "=r"(r1), "=r"(r2), "=r"(r3) : "r"(addr));
}

// ---------------------------------------------------------------------------
// preprocessing kernels
// ---------------------------------------------------------------------------
__global__ void pack_fp16_kernel(const float* __restrict__ in, __half* __restrict__ out,
                                 int n4, int cols) {
    int i = blockIdx.x * blockDim.x + threadIdx.x;
    if (i < n4) {
        int row = (i * 4) / cols, col = (i * 4) % cols;
        float4 v = *(const float4*)(in + (size_t)i * 4);
        __half2 h0 = __floats2half2_rn(v.x, v.y);
        __half2 h1 = __floats2half2_rn(v.z, v.w);
        __half* p = out + (size_t)row * K_TOT + col;
        *(__half2*)(p)     = h0;
        *(__half2*)(p + 2) = h1;
    }
}

__global__ void pack_wtail_kernel(const float* __restrict__ loraB, __half* __restrict__ wcat) {
    int i = blockIdx.x * blockDim.x + threadIdx.x;  // 4096*64
    int row = i >> 6, col = i & 63;
    __half v = (col < RANK) ? __float2half(loraB[row * RANK + col]) : __half(0.f);
    wcat[(size_t)row * K_TOT + 1024 + col] = v;
}

// split-K partial with smem staging:
// tp[kc][m][r] = sum_{k in slice kc} x[m,k]*A[r,k]
// block: 64 m-rows x 16 ranks x 128 k.  thread(tx=rank, ty) -> 4 m-rows.
__global__ __launch_bounds__(256)
void lora_part_kernel(const float* __restrict__ x,
                      const float* __restrict__ loraA,
                      float* __restrict__ tp, int M) {
    __shared__ __align__(16) float xs[LROWS * XPITCH];   // 64 x 132
    __shared__ __align__(16) float as[RANK * APITCH];    // 16 x 132

    const int tid = threadIdx.x;
    const int kc  = blockIdx.y;
    const int k0  = kc * LKS;
    const int mb  = blockIdx.x * LROWS;

    // stage x tile: 64 rows x 128 floats = 2048 float4, 8 per thread
#pragma unroll
    for (int j = 0; j < 8; j++) {
        int i = tid + j * 256;           // 0..2047
        int row = i >> 5, c4 = i & 31;
        float4 v = (mb + row < M)
            ? *(const float4*)(x + (size_t)(mb + row) * IN_F + k0 + c4 * 4)
            : make_float4(0, 0, 0, 0);
        *(float4*)(xs + row * XPITCH + c4 * 4) = v;
    }
    // stage A tile: 16 rows x 128 floats = 512 float4, 2 per thread
#pragma unroll
    for (int j = 0; j < 2; j++) {
        int i = tid + j * 256;           // 0..511
        int row = i >> 5, c4 = i & 31;
        float4 v = *(const float4*)(loraA + (size_t)row * IN_F + k0 + c4 * 4);
        *(float4*)(as + row * APITCH + c4 * 4) = v;
    }
    __syncthreads();

    const int tx = tid & 15;             // rank
    const int ty = tid >> 4;             // 0..15 -> 4 rows each
    const int r0 = ty * 4;

    float s0 = 0.f, s1 = 0.f, s2 = 0.f, s3 = 0.f;
    const float* a = as + tx * APITCH;
    const float* x0 = xs + (r0 + 0) * XPITCH;
    const float* x1 = xs + (r0 + 1) * XPITCH;
    const float* x2 = xs + (r0 + 2) * XPITCH;
    const float* x3 = xs + (r0 + 3) * XPITCH;

#pragma unroll
    for (int k = 0; k < LKS; k += 4) {
        float4 av = *(const float4*)(a + k);
        float4 v0 = *(const float4*)(x0 + k);
        float4 v1 = *(const float4*)(x1 + k);
        float4 v2 = *(const float4*)(x2 + k);
        float4 v3 = *(const float4*)(x3 + k);
        s0 += av.x * v0.x + av.y * v0.y + av.z * v0.z + av.w * v0.w;
        s1 += av.x * v1.x + av.y * v1.y + av.z * v1.z + av.w * v1.w;
        s2 += av.x * v2.x + av.y * v2.y + av.z * v2.z + av.w * v2.w;
        s3 += av.x * v3.x + av.y * v3.y + av.z * v3.z + av.w * v3.w;
    }

    float* dst = tp + (size_t)kc * 2048 * RANK;
    int m = mb + r0;
    if (m + 0 < M) dst[(m + 0) * RANK + tx] = s0;
    if (m + 1 < M) dst[(m + 1) * RANK + tx] = s1;
    if (m + 2 < M) dst[(m + 2) * RANK + tx] = s2;
    if (m + 3 < M) dst[(m + 3) * RANK + tx] = s3;
}

// reduce partials -> fp16 tail of xcat (+ zero pad)
__global__ void lora_fin_kernel(const float* __restrict__ tp,
                                __half* __restrict__ xcat, int M) {
    int i = blockIdx.x * blockDim.x + threadIdx.x;
    int m = i >> 4, r = i & 15;
    if (m >= M) return;
    float s = 0.f;
#pragma unroll
    for (int kc = 0; kc < KSPLIT; kc++)
        s += tp[(size_t)kc * 2048 * RANK + m * RANK + r];
    __half* row = xcat + (size_t)m * K_TOT + 1024;
    row[r] = __float2half(s * LORA_SCALE);
#pragma unroll
    for (int q = 0; q < 3; q++) row[16 + r * 3 + q] = __half(0.f);
}

// ---------------------------------------------------------------------------
// main GEMM: fp16 mma.m16n8k16, 128x128x64 tiles, 3-stage cp.async
// ---------------------------------------------------------------------------
__global__ __launch_bounds__(256, 2)
void dora_f16_kernel(const __half* __restrict__ xcat,
                     const __half* __restrict__ wcat,
                     const float* __restrict__ mag,
                     const float* __restrict__ bias,
                     float* __restrict__ out, int M) {
    extern __shared__ __align__(1024) char smraw[];

    const int tid   = threadIdx.x;
    const int lane  = tid & 31;
    const int warp  = tid >> 5;
    const int warpM = warp >> 2;   // 0..1 -> m offset 64*warpM
    const int warpN = warp & 3;    // 0..3 -> n offset 32*warpN
    const int bm = blockIdx.y * BM;
    const int bn = blockIdx.x * BN;

    float acc[4][4][4];
#pragma unroll
    for (int i = 0; i < 4; i++)
#pragma unroll
        for (int j = 0; j < 4; j++)
#pragma unroll
            for (int k = 0; k < 4; k++) acc[i][j][k] = 0.f;

    const int ldr = tid >> 1;            // 0..127 row
    const int ldc = (tid & 1) * 4;       // chunk group 0 or 4

    auto load_stage = [&](int s, int it) {
        uint32_t st = smem_u32(smraw) + s * STAGE_BYTES;
        const int kb = it * 128;  // byte offset in row
        const __half* xrow = xcat + (size_t)(bm + ldr) * K_TOT;
        const __half* wrow = wcat + (size_t)(bn + ldr) * K_TOT;
        int xbytes = (bm + ldr) < M ? 16 : 0;
#pragma unroll
        for (int j = 0; j < 4; j++) {
            int c = ldc + j;
            uint32_t dst = st + (uint32_t)(ldr * 128 + (((c ^ (ldr & 7)) << 4)));
            cp_async16(dst, (const char*)xrow + kb + c * 16, xbytes);
            uint32_t dstB = dst + 16384;
            cp_async16(dstB, (const char*)wrow + kb + c * 16, 16);
        }
    };

    load_stage(0, 0); cp_commit();
    load_stage(1, 1); cp_commit();

    const int lg = lane >> 3, lr = lane & 7;

    uint32_t offA[4];   // per m-tile
#pragma unroll
    for (int mi = 0; mi < 4; mi++) {
        int row = warpM * 64 + mi * 16 + (lg & 1) * 8 + lr;
        int grp = lg >> 1;
        offA[mi] = (uint32_t)(row * 128 + (((grp ^ (row & 7)) << 4)));
    }
    uint32_t offB[2];   // per n-tile pair
#pragma unroll
    for (int np = 0; np < 2; np++) {
        int row = warpN * 32 + np * 16 + (lg >> 1) * 8 + lr;
        int grp = lg & 1;
        offB[np] = (uint32_t)(16384 + row * 128 + (((grp ^ (row & 7)) << 4)));
    }

    const uint32_t sbase = smem_u32(smraw);

    int sc = 0, sl = 2;
    for (int it = 0; it < NITER; ++it) {
        cp_wait<1>();
        __syncthreads();
        const uint32_t stage = sbase + sc * STAGE_BYTES;

#pragma unroll
        for (int kk = 0; kk < 4; kk++) {
            const uint32_t kx = (uint32_t)(kk * 32);
            uint32_t a[4][4], b[4][2];
#pragma unroll
            for (int mi = 0; mi < 4; mi++)
                ldsm_x4(a[mi][0], a[mi][1], a[mi][2], a[mi][3],
                        stage + (offA[mi] ^ kx));
#pragma unroll
            for (int np = 0; np < 2; np++)
                ldsm_x4(b[2*np][0], b[2*np][1], b[2*np+1][0], b[2*np+1][1],
                        stage + (offB[np] ^ kx));
#pragma unroll
            for (int mi = 0; mi < 4; mi++)
#pragma unroll
                for (int ni = 0; ni < 4; ni++)
                    asm volatile(
                        "mma.sync.aligned.m16n8k16.row.col.f32.f16.f16.f32 "
                        "{%0,%1,%2,%3}, {%4,%5,%6,%7}, {%8,%9}, {%0,%1,%2,%3};"
                        : "+f"(acc[mi][ni][0]), "+f"(acc[mi][ni][1]),
                          "+f"(acc[mi][ni][2]), "+f"(acc[mi][ni][3])
                        : "r"(a[mi][0]), "r"(a[mi][1]), "r"(a[mi][2]), "r"(a[mi][3]),
                          "r"(b[ni][0]), "r"(b[ni][1]));
        }

        int jn = it + 2;
        if (jn < NITER) load_stage(sl, jn);
        cp_commit();
        sc = (sc + 1) == STAGES ? 0 : sc + 1;
        sl = (sl + 1) == STAGES ? 0 : sl + 1;
    }

    // ---------------- epilogue: *mag + bias, store ----------------
    __syncthreads();
    float* magS  = (float*)smraw;
    float* biasS = magS + BN;
    if (tid < BN) { magS[tid] = mag[bn + tid]; biasS[tid] = bias[bn + tid]; }
    __syncthreads();

    const int mrow = warpM * 64 + (lane >> 2);
    const int ocol = warpN * 32 + 2 * (lane & 3);

#pragma unroll
    for (int ni = 0; ni < 4; ni++) {
        int ol = ocol + ni * 8;
        float mg0 = magS[ol],  mg1 = magS[ol + 1];
        float bi0 = biasS[ol], bi1 = biasS[ol + 1];
#pragma unroll
        for (int mi = 0; mi < 4; mi++)
#pragma unroll
            for (int h = 0; h < 2; h++) {
                int m = bm + mrow + mi * 16 + 8 * h;
                if (m < M) {
                    float2 v;
                    v.x = acc[mi][ni][2 * h + 0] * mg0 + bi0;
                    v.y = acc[mi][ni][2 * h + 1] * mg1 + bi1;
                    *(float2*)(out + (size_t)m * OUT_F + bn + ol) = v;
                }
            }
    }
}

extern "C" void kernel_launch(void* const* d_in, const int* in_sizes, int n_in,
                              void* d_out, int out_size) {
    const float* x     = (const float*)d_in[0];
    const float* wd    = (const float*)d_in[1];
    const float* mag   = (const float*)d_in[2];
    const float* loraA = (const float*)d_in[3];
    const float* loraB = (const float*)d_in[4];
    const float* bias  = (const float*)d_in[5];
    float* out = (float*)d_out;

    const int M = in_sizes[0] / IN_F;

    __half *xcat, *wcat;
    float* tp;
    cudaGetSymbolAddress((void**)&xcat, g_xcat);
    cudaGetSymbolAddress((void**)&wcat, g_wcat);
    cudaGetSymbolAddress((void**)&tp, g_tp);

    int nx4 = (M * IN_F) / 4;
    int nw4 = (OUT_F * IN_F) / 4;
    pack_fp16_kernel<<<(nw4 + 255) / 256, 256>>>(wd, wcat, nw4, IN_F);
    pack_fp16_kernel<<<(nx4 + 255) / 256, 256>>>(x, xcat, nx4, IN_F);
    pack_wtail_kernel<<<(OUT_F * 64) / 256, 256>>>(loraB, wcat);

    dim3 lgrid((M + LROWS - 1) / LROWS, KSPLIT);
    lora_part_kernel<<<lgrid, 256>>>(x, loraA, tp, M);
    lora_fin_kernel<<<(M * RANK + 255) / 256, 256>>>(tp, xcat, M);

    static int smem_set = 0;
    if (!smem_set) {
        cudaFuncSetAttribute(dora_f16_kernel,
                             cudaFuncAttributeMaxDynamicSharedMemorySize, SMEM_BYTES);
        smem_set = 1;
    }
    dim3 grid(OUT_F / BN, (M + BM - 1) / BM);
    dora_f16_kernel<<<grid, 256, SMEM_BYTES>>>(xcat, wcat, mag, bias, out, M);
}

// round 13
// speedup vs baseline: 7.4886x; 1.0286x over previous
#include <cuda_runtime.h>
#include <cuda_fp16.h>
#include <cstdint>

// y = (x @ Wd^T + s*(x @ A^T) @ B^T) * mag + bias
// mag folded into packed weights:
//   wcat = [fp16(Wd*mag) | fp16(B*mag) | 0]   (K_TOT=1088)
//   xcat = [fp16(x)      | fp16(t)     | 0],  t = s * x @ A^T
// -> one fp16 mma.sync GEMM (fp32 accum), epilogue = +bias.

#define IN_F   1024
#define OUT_F  4096
#define RANK   16
#define LORA_SCALE 0.8f

#define K_TOT  1088           // 17 * 64
#define NITER  17
#define STAGES 3
#define BM     128
#define BN     128
#define STAGE_BYTES 32768     // A 16KB + B 16KB
#define SMEM_BYTES (STAGES * STAGE_BYTES)

#define KSPLIT 16             // lora split-K factor (1024/64)
#define LKS    (IN_F / KSPLIT)   // 64 k per slice
#define LROWS  64
#define XPITCH 68
#define APITCH 68

__device__ __align__(16) __half g_xcat[2048 * K_TOT];
__device__ __align__(16) __half g_wcat[OUT_F * K_TOT];
__device__ __align__(16) float  g_tp[KSPLIT * 2048 * RANK];

// ---------------------------------------------------------------------------
// helpers
// ---------------------------------------------------------------------------
__device__ __forceinline__ uint32_t smem_u32(const void* p) {
    return (uint32_t)__cvta_generic_to_shared(p);
}
__device__ __forceinline__ void cp_async16(uint32_t dst, const void* src, int src_bytes) {
    asm volatile("cp.async.cg.shared.global [%0], [%1], 16, %2;\n"
                 :: "r"(dst), "l"(src), "r"(src_bytes));
}
__device__ __forceinline__ void cp_commit() { asm volatile("cp.async.commit_group;\n"); }
template <int N>
__device__ __forceinline__ void cp_wait() { asm volatile("cp.async.wait_group %0;\n" :: "n"(N)); }

__device__ __forceinline__ void ldsm_x4(uint32_t& r0, uint32_t& r1, uint32_t& r2, uint32_t& r3,
                                        uint32_t addr) {
    asm volatile("ldmatrix.sync.aligned.m8n8.x4.shared.b16 {%0,%1,%2,%3}, [%4];"
                 : "=r"(r0), "=r"(r1), "=r"(r2), "=r"(r3) : "r"(addr));
}

// ---------------------------------------------------------------------------
// preprocessing kernels
// ---------------------------------------------------------------------------
__global__ void pack_x_kernel(const float* __restrict__ in, __half* __restrict__ out, int n4) {
    int i = blockIdx.x * blockDim.x + threadIdx.x;
    if (i < n4) {
        int row = (i * 4) / IN_F, col = (i * 4) % IN_F;
        float4 v = *(const float4*)(in + (size_t)i * 4);
        __half* p = out + (size_t)row * K_TOT + col;
        *(__half2*)(p)     = __floats2half2_rn(v.x, v.y);
        *(__half2*)(p + 2) = __floats2half2_rn(v.z, v.w);
    }
}

// wcat: head = fp16(Wd[row]*mag[row]); chunks 0..15 also write the tail
// (cols 1024..1087 = fp16(loraB*mag) for first 16, zeros after).
__global__ void pack_w_kernel(const float* __restrict__ wd, const float* __restrict__ mag,
                              const float* __restrict__ loraB,
                              __half* __restrict__ wcat) {
    int i = blockIdx.x * blockDim.x + threadIdx.x;   // over n4 = OUT_F*IN_F/4
    int row = (i * 4) / IN_F, col = (i * 4) % IN_F;
    float m = mag[row];
    float4 v = *(const float4*)(wd + (size_t)i * 4);
    __half* p = wcat + (size_t)row * K_TOT + col;
    *(__half2*)(p)     = __floats2half2_rn(v.x * m, v.y * m);
    *(__half2*)(p + 2) = __floats2half2_rn(v.z * m, v.w * m);

    int chunk = col >> 2;           // 0..255
    if (chunk < 16) {               // chunk c -> tail cols 4c..4c+3
        int j0 = chunk * 4;
        __half* tp = wcat + (size_t)row * K_TOT + 1024 + j0;
#pragma unroll
        for (int q = 0; q < 4; q++) {
            int j = j0 + q;
            tp[q] = (j < RANK) ? __float2half(loraB[row * RANK + j] * m) : __half(0.f);
        }
    }
}

// split-K partial with smem staging: tp[kc][m][r] = sum_{k slice} x[m,k]*A[r,k]
__global__ __launch_bounds__(256)
void lora_part_kernel(const float* __restrict__ x,
                      const float* __restrict__ loraA,
                      float* __restrict__ tp, int M) {
    __shared__ __align__(16) float xs[LROWS * XPITCH];
    __shared__ __align__(16) float as[RANK * APITCH];

    const int tid = threadIdx.x;
    const int kc  = blockIdx.y;
    const int k0  = kc * LKS;
    const int mb  = blockIdx.x * LROWS;

    // stage x tile: 64 rows x 64 floats = 1024 float4, 4 per thread
#pragma unroll
    for (int j = 0; j < 4; j++) {
        int i = tid + j * 256;
        int row = i >> 4, c4 = i & 15;
        float4 v = (mb + row < M)
            ? *(const float4*)(x + (size_t)(mb + row) * IN_F + k0 + c4 * 4)
            : make_float4(0, 0, 0, 0);
        *(float4*)(xs + row * XPITCH + c4 * 4) = v;
    }
    // stage A tile: 16 rows x 64 floats = 256 float4, 1 per thread
    {
        int row = tid >> 4, c4 = tid & 15;
        float4 v = *(const float4*)(loraA + (size_t)row * IN_F + k0 + c4 * 4);
        *(float4*)(as + row * APITCH + c4 * 4) = v;
    }
    __syncthreads();

    const int tx = tid & 15;             // rank
    const int ty = tid >> 4;             // 0..15 -> 4 rows each
    const int r0 = ty * 4;

    float s0 = 0.f, s1 = 0.f, s2 = 0.f, s3 = 0.f;
    const float* a  = as + tx * APITCH;
    const float* x0 = xs + (r0 + 0) * XPITCH;
    const float* x1 = xs + (r0 + 1) * XPITCH;
    const float* x2 = xs + (r0 + 2) * XPITCH;
    const float* x3 = xs + (r0 + 3) * XPITCH;

#pragma unroll
    for (int k = 0; k < LKS; k += 4) {
        float4 av = *(const float4*)(a + k);
        float4 v0 = *(const float4*)(x0 + k);
        float4 v1 = *(const float4*)(x1 + k);
        float4 v2 = *(const float4*)(x2 + k);
        float4 v3 = *(const float4*)(x3 + k);
        s0 += av.x * v0.x + av.y * v0.y + av.z * v0.z + av.w * v0.w;
        s1 += av.x * v1.x + av.y * v1.y + av.z * v1.z + av.w * v1.w;
        s2 += av.x * v2.x + av.y * v2.y + av.z * v2.z + av.w * v2.w;
        s3 += av.x * v3.x + av.y * v3.y + av.z * v3.z + av.w * v3.w;
    }

    float* dst = tp + (size_t)kc * 2048 * RANK;
    int m = mb + r0;
    if (m + 0 < M) dst[(m + 0) * RANK + tx] = s0;
    if (m + 1 < M) dst[(m + 1) * RANK + tx] = s1;
    if (m + 2 < M) dst[(m + 2) * RANK + tx] = s2;
    if (m + 3 < M) dst[(m + 3) * RANK + tx] = s3;
}

// reduce partials -> fp16 tail of xcat (+ zero pad)
__global__ void lora_fin_kernel(const float* __restrict__ tp,
                                __half* __restrict__ xcat, int M) {
    int i = blockIdx.x * blockDim.x + threadIdx.x;
    int m = i >> 4, r = i & 15;
    if (m >= M) return;
    float s = 0.f;
#pragma unroll
    for (int kc = 0; kc < KSPLIT; kc++)
        s += tp[(size_t)kc * 2048 * RANK + m * RANK + r];
    __half* row = xcat + (size_t)m * K_TOT + 1024;
    row[r] = __float2half(s * LORA_SCALE);
#pragma unroll
    for (int q = 0; q < 3; q++) row[16 + r * 3 + q] = __half(0.f);
}

// ---------------------------------------------------------------------------
// main GEMM: fp16 mma.m16n8k16, 128x128x64 tiles, 3-stage cp.async
// ---------------------------------------------------------------------------
__global__ __launch_bounds__(256, 2)
void dora_f16_kernel(const __half* __restrict__ xcat,
                     const __half* __restrict__ wcat,
                     const float* __restrict__ bias,
                     float* __restrict__ out, int M) {
    extern __shared__ __align__(1024) char smraw[];

    const int tid   = threadIdx.x;
    const int lane  = tid & 31;
    const int warp  = tid >> 5;
    const int warpM = warp >> 2;   // 0..1 -> m offset 64*warpM
    const int warpN = warp & 3;    // 0..3 -> n offset 32*warpN
    const int bm = blockIdx.y * BM;
    const int bn = blockIdx.x * BN;

    float acc[4][4][4];
#pragma unroll
    for (int i = 0; i < 4; i++)
#pragma unroll
        for (int j = 0; j < 4; j++)
#pragma unroll
            for (int k = 0; k < 4; k++) acc[i][j][k] = 0.f;

    const int ldr = tid >> 1;            // 0..127 row
    const int ldc = (tid & 1) * 4;       // chunk group 0 or 4

    auto load_stage = [&](int s, int it) {
        uint32_t st = smem_u32(smraw) + s * STAGE_BYTES;
        const int kb = it * 128;  // byte offset in row
        const __half* xrow = xcat + (size_t)(bm + ldr) * K_TOT;
        const __half* wrow = wcat + (size_t)(bn + ldr) * K_TOT;
        int xbytes = (bm + ldr) < M ? 16 : 0;
#pragma unroll
        for (int j = 0; j < 4; j++) {
            int c = ldc + j;
            uint32_t dst = st + (uint32_t)(ldr * 128 + (((c ^ (ldr & 7)) << 4)));
            cp_async16(dst, (const char*)xrow + kb + c * 16, xbytes);
            cp_async16(dst + 16384, (const char*)wrow + kb + c * 16, 16);
        }
    };

    load_stage(0, 0); cp_commit();
    load_stage(1, 1); cp_commit();

    const int lg = lane >> 3, lr = lane & 7;

    uint32_t offA[4];   // per m-tile
#pragma unroll
    for (int mi = 0; mi < 4; mi++) {
        int row = warpM * 64 + mi * 16 + (lg & 1) * 8 + lr;
        int grp = lg >> 1;
        offA[mi] = (uint32_t)(row * 128 + (((grp ^ (row & 7)) << 4)));
    }
    uint32_t offB[2];   // per n-tile pair
#pragma unroll
    for (int np = 0; np < 2; np++) {
        int row = warpN * 32 + np * 16 + (lg >> 1) * 8 + lr;
        int grp = lg & 1;
        offB[np] = (uint32_t)(16384 + row * 128 + (((grp ^ (row & 7)) << 4)));
    }

    const uint32_t sbase = smem_u32(smraw);

    auto do_kstep = [&](uint32_t stage, int kk) {
        const uint32_t kx = (uint32_t)(kk * 32);
        uint32_t a[4][4], b[4][2];
#pragma unroll
        for (int mi = 0; mi < 4; mi++)
            ldsm_x4(a[mi][0], a[mi][1], a[mi][2], a[mi][3],
                    stage + (offA[mi] ^ kx));
#pragma unroll
        for (int np = 0; np < 2; np++)
            ldsm_x4(b[2*np][0], b[2*np][1], b[2*np+1][0], b[2*np+1][1],
                    stage + (offB[np] ^ kx));
#pragma unroll
        for (int mi = 0; mi < 4; mi++)
#pragma unroll
            for (int ni = 0; ni < 4; ni++)
                asm volatile(
                    "mma.sync.aligned.m16n8k16.row.col.f32.f16.f16.f32 "
                    "{%0,%1,%2,%3}, {%4,%5,%6,%7}, {%8,%9}, {%0,%1,%2,%3};"
                    : "+f"(acc[mi][ni][0]), "+f"(acc[mi][ni][1]),
                      "+f"(acc[mi][ni][2]), "+f"(acc[mi][ni][3])
                    : "r"(a[mi][0]), "r"(a[mi][1]), "r"(a[mi][2]), "r"(a[mi][3]),
                      "r"(b[ni][0]), "r"(b[ni][1]));
    };

    int sc = 0, sl = 2;
    for (int it = 0; it < NITER; ++it) {
        cp_wait<1>();
        __syncthreads();
        const uint32_t stage = sbase + sc * STAGE_BYTES;

        if (it < NITER - 1) {
#pragma unroll
            for (int kk = 0; kk < 4; kk++) do_kstep(stage, kk);
        } else {
            // last iter: only cols 1024..1039 are nonzero -> 1 k-step
            do_kstep(stage, 0);
        }

        int jn = it + 2;
        if (jn < NITER) load_stage(sl, jn);
        cp_commit();
        sc = (sc + 1) == STAGES ? 0 : sc + 1;
        sl = (sl + 1) == STAGES ? 0 : sl + 1;
    }

    // ---------------- epilogue: +bias, store ----------------
    __syncthreads();
    float* biasS = (float*)smraw;
    if (tid < BN) biasS[tid] = bias[bn + tid];
    __syncthreads();

    const int mrow = warpM * 64 + (lane >> 2);
    const int ocol = warpN * 32 + 2 * (lane & 3);

#pragma unroll
    for (int ni = 0; ni < 4; ni++) {
        int ol = ocol + ni * 8;
        float bi0 = biasS[ol], bi1 = biasS[ol + 1];
#pragma unroll
        for (int mi = 0; mi < 4; mi++)
#pragma unroll
            for (int h = 0; h < 2; h++) {
                int m = bm + mrow + mi * 16 + 8 * h;
                if (m < M) {
                    float2 v;
                    v.x = acc[mi][ni][2 * h + 0] + bi0;
                    v.y = acc[mi][ni][2 * h + 1] + bi1;
                    *(float2*)(out + (size_t)m * OUT_F + bn + ol) = v;
                }
            }
    }
}

extern "C" void kernel_launch(void* const* d_in, const int* in_sizes, int n_in,
                              void* d_out, int out_size) {
    const float* x     = (const float*)d_in[0];
    const float* wd    = (const float*)d_in[1];
    const float* mag   = (const float*)d_in[2];
    const float* loraA = (const float*)d_in[3];
    const float* loraB = (const float*)d_in[4];
    const float* bias  = (const float*)d_in[5];
    float* out = (float*)d_out;

    const int M = in_sizes[0] / IN_F;

    __half *xcat, *wcat;
    float* tp;
    cudaGetSymbolAddress((void**)&xcat, g_xcat);
    cudaGetSymbolAddress((void**)&wcat, g_wcat);
    cudaGetSymbolAddress((void**)&tp, g_tp);

    int nx4 = (M * IN_F) / 4;
    int nw4 = (OUT_F * IN_F) / 4;
    pack_w_kernel<<<(nw4 + 255) / 256, 256>>>(wd, mag, loraB, wcat);
    pack_x_kernel<<<(nx4 + 255) / 256, 256>>>(x, xcat, nx4);

    dim3 lgrid((M + LROWS - 1) / LROWS, KSPLIT);
    lora_part_kernel<<<lgrid, 256>>>(x, loraA, tp, M);
    lora_fin_kernel<<<(M * RANK + 255) / 256, 256>>>(tp, xcat, M);

    static int smem_set = 0;
    if (!smem_set) {
        cudaFuncSetAttribute(dora_f16_kernel,
                             cudaFuncAttributeMaxDynamicSharedMemorySize, SMEM_BYTES);
        smem_set = 1;
    }
    dim3 grid(OUT_F / BN, (M + BM - 1) / BM);
    dora_f16_kernel<<<grid, 256, SMEM_BYTES>>>(xcat, wcat, bias, out, M);
}